// round 16
// baseline (speedup 1.0000x reference)
#include <cuda_runtime.h>
#include <cuda_fp16.h>
#include <math.h>
#include <cstdint>

#define SEQ   512
#define BATCH 64
#define INDIM 1024
#define HID   1024

// ---------------- device scratch (static: allowed) ----------------
__device__ __half g_Xhi[SEQ * BATCH * INDIM];
__device__ __half g_Xlo[SEQ * BATCH * INDIM];
__device__ __half g_Whi[HID * INDIM];
__device__ __half g_Wlo[HID * INDIM];
__device__ __half g_Hhi[2][BATCH * HID];
__device__ __half g_Hlo[2][BATCH * HID];

// per-bt-group barrier state, padded: counter at [bt*64], phase at [bt*64+32]
__device__ unsigned g_cnt[256];
__device__ volatile unsigned g_ph[256];

__global__ void init_sync_kernel() {
    g_cnt[threadIdx.x] = 0u;
    g_ph[threadIdx.x]  = 0u;
}

// ---------------------------------------------------------------------------
__device__ __forceinline__ void cp_async16(void* smem_dst, const void* gsrc) {
    unsigned d = (unsigned)__cvta_generic_to_shared(smem_dst);
    asm volatile("cp.async.cg.shared.global [%0], [%1], 16;\n" :: "r"(d), "l"(gsrc));
}
__device__ __forceinline__ void cp_commit() { asm volatile("cp.async.commit_group;\n"); }
__device__ __forceinline__ void cp_wait0()  { asm volatile("cp.async.wait_group 0;\n"); }
__device__ __forceinline__ void cp_wait1()  { asm volatile("cp.async.wait_group 1;\n"); }

__device__ __forceinline__ float mask13(float v) {
    return __uint_as_float(__float_as_uint(v) & 0xFFFFE000u);
}

__device__ __forceinline__ void mma_f16(float* d,
                                        uint32_t a0, uint32_t a1, uint32_t a2, uint32_t a3,
                                        uint32_t b0, uint32_t b1) {
    asm volatile(
        "mma.sync.aligned.m16n8k16.row.col.f32.f16.f16.f32 "
        "{%0,%1,%2,%3}, {%4,%5,%6,%7}, {%8,%9}, {%0,%1,%2,%3};"
        : "+f"(d[0]), "+f"(d[1]), "+f"(d[2]), "+f"(d[3])
        : "r"(a0), "r"(a1), "r"(a2), "r"(a3), "r"(b0), "r"(b1));
}

__device__ __forceinline__ void ldsm_x4(uint32_t* r, uint32_t a) {
    asm volatile("ldmatrix.sync.aligned.m8n8.x4.shared.b16 {%0,%1,%2,%3}, [%4];"
        : "=r"(r[0]), "=r"(r[1]), "=r"(r[2]), "=r"(r[3]) : "r"(a));
}
__device__ __forceinline__ void ldsm_x2(uint32_t* r, uint32_t a) {
    asm volatile("ldmatrix.sync.aligned.m8n8.x2.shared.b16 {%0,%1}, [%2];"
        : "=r"(r[0]), "=r"(r[1]) : "r"(a));
}

// ---------------------------------------------------------------------------
// Split kernels: fp32 -> fp16 hi/lo planes
// ---------------------------------------------------------------------------
__global__ void split_x_kernel(const float* __restrict__ src) {
    int i = blockIdx.x * 256 + threadIdx.x;
    float4 v = ((const float4*)src)[i];
    float h0 = mask13(v.x), h1 = mask13(v.y), h2 = mask13(v.z), h3 = mask13(v.w);
    ((__half2*)g_Xhi)[2 * i]     = __floats2half2_rn(h0, h1);
    ((__half2*)g_Xhi)[2 * i + 1] = __floats2half2_rn(h2, h3);
    ((__half2*)g_Xlo)[2 * i]     = __floats2half2_rn(v.x - h0, v.y - h1);
    ((__half2*)g_Xlo)[2 * i + 1] = __floats2half2_rn(v.z - h2, v.w - h3);
}
__global__ void split_w_kernel(const float* __restrict__ src) {
    int i = blockIdx.x * 256 + threadIdx.x;
    float4 v = ((const float4*)src)[i];
    float h0 = mask13(v.x), h1 = mask13(v.y), h2 = mask13(v.z), h3 = mask13(v.w);
    ((__half2*)g_Whi)[2 * i]     = __floats2half2_rn(h0, h1);
    ((__half2*)g_Whi)[2 * i + 1] = __floats2half2_rn(h2, h3);
    ((__half2*)g_Wlo)[2 * i]     = __floats2half2_rn(v.x - h0, v.y - h1);
    ((__half2*)g_Wlo)[2 * i + 1] = __floats2half2_rn(v.z - h2, v.w - h3);
}

// ---------------------------------------------------------------------------
// Phase 1: C = x @ W_ih^T + bias. fp16 3-pass MMA, scalar LDS loads (R14).
// ---------------------------------------------------------------------------
#define P1P 40
__global__ __launch_bounds__(256) void gemm_xw_f16_kernel(
    const float* __restrict__ bih,
    const float* __restrict__ bhh,
    float* __restrict__ C)
{
    extern __shared__ __half sh[];
    __half* Ahi = sh;
    __half* Alo = sh + 10240;
    __half* Bhi = sh + 20480;
    __half* Blo = sh + 30720;

    const int tid    = threadIdx.x;
    const int lane   = tid & 31;
    const int wid    = tid >> 5;
    const int g      = lane >> 2;
    const int tig    = lane & 3;
    const int warp_m = wid & 1;
    const int warp_n = wid >> 1;
    const int bm     = blockIdx.y * 128;
    const int bn     = blockIdx.x * 128;

    float acc[4][4][4];
#pragma unroll
    for (int i = 0; i < 4; i++)
#pragma unroll
        for (int j = 0; j < 4; j++)
#pragma unroll
            for (int c = 0; c < 4; c++) acc[i][j][c] = 0.0f;

    const int srow = tid >> 2;
    const int sch  = tid & 3;

    auto stage = [&](int c) {
        const int bo = (c & 1) * 5120;
        const int kc = c * 32;
#pragma unroll
        for (int u = 0; u < 2; u++) {
            int row = srow + u * 64;
            size_t aoff = (size_t)(bm + row) * INDIM + kc + sch * 8;
            size_t boff = (size_t)(bn + row) * INDIM + kc + sch * 8;
            cp_async16(Ahi + bo + row * P1P + sch * 8, g_Xhi + aoff);
            cp_async16(Alo + bo + row * P1P + sch * 8, g_Xlo + aoff);
            cp_async16(Bhi + bo + row * P1P + sch * 8, g_Whi + boff);
            cp_async16(Blo + bo + row * P1P + sch * 8, g_Wlo + boff);
        }
        cp_commit();
    };

    stage(0);

    for (int c = 0; c < INDIM / 32; c++) {
        if (c + 1 < INDIM / 32) { stage(c + 1); cp_wait1(); }
        else                    { cp_wait0(); }
        __syncthreads();

        const int bo = (c & 1) * 5120;
        const __half* Aph = Ahi + bo + warp_m * 64 * P1P;
        const __half* Apl = Alo + bo + warp_m * 64 * P1P;
        const __half* Bph = Bhi + bo + warp_n * 32 * P1P;
        const __half* Bpl = Blo + bo + warp_n * 32 * P1P;

#pragma unroll
        for (int kg = 0; kg < 2; kg++) {
            const int ko = kg * 16 + 2 * tig;

            uint32_t ah[4][4], al[4][4];
#pragma unroll
            for (int mt = 0; mt < 4; mt++) {
                int base = (mt * 16 + g) * P1P + ko;
                ah[mt][0] = *(const uint32_t*)&Aph[base];
                ah[mt][1] = *(const uint32_t*)&Aph[base + 8 * P1P];
                ah[mt][2] = *(const uint32_t*)&Aph[base + 8];
                ah[mt][3] = *(const uint32_t*)&Aph[base + 8 * P1P + 8];
                al[mt][0] = *(const uint32_t*)&Apl[base];
                al[mt][1] = *(const uint32_t*)&Apl[base + 8 * P1P];
                al[mt][2] = *(const uint32_t*)&Apl[base + 8];
                al[mt][3] = *(const uint32_t*)&Apl[base + 8 * P1P + 8];
            }
            uint32_t bh[4][2], bl[4][2];
#pragma unroll
            for (int nt = 0; nt < 4; nt++) {
                int sb = (nt * 8 + g) * P1P + ko;
                bh[nt][0] = *(const uint32_t*)&Bph[sb];
                bh[nt][1] = *(const uint32_t*)&Bph[sb + 8];
                bl[nt][0] = *(const uint32_t*)&Bpl[sb];
                bl[nt][1] = *(const uint32_t*)&Bpl[sb + 8];
            }
#pragma unroll
            for (int mt = 0; mt < 4; mt++) {
#pragma unroll
                for (int nt = 0; nt < 4; nt++) {
                    mma_f16(acc[mt][nt], ah[mt][0], ah[mt][1], ah[mt][2], ah[mt][3],
                            bh[nt][0], bh[nt][1]);
                    mma_f16(acc[mt][nt], al[mt][0], al[mt][1], al[mt][2], al[mt][3],
                            bh[nt][0], bh[nt][1]);
                    mma_f16(acc[mt][nt], ah[mt][0], ah[mt][1], ah[mt][2], ah[mt][3],
                            bl[nt][0], bl[nt][1]);
                }
            }
        }
        __syncthreads();
    }

#pragma unroll
    for (int nt = 0; nt < 4; nt++) {
        const int n0 = bn + warp_n * 32 + nt * 8 + 2 * tig;
        const float bv0 = bih[n0] + bhh[n0];
        const float bv1 = bih[n0 + 1] + bhh[n0 + 1];
#pragma unroll
        for (int mt = 0; mt < 4; mt++) {
            const int m0 = bm + warp_m * 64 + mt * 16 + g;
            float2 lo2, hi2;
            lo2.x = acc[mt][nt][0] + bv0;
            lo2.y = acc[mt][nt][1] + bv1;
            hi2.x = acc[mt][nt][2] + bv0;
            hi2.y = acc[mt][nt][3] + bv1;
            *(float2*)(C + (size_t)m0 * HID + n0)       = lo2;
            *(float2*)(C + (size_t)(m0 + 8) * HID + n0) = hi2;
        }
    }
}

// ---------------------------------------------------------------------------
// Phase 2: persistent recurrence, 512 threads / 16 warps = (nt 0..3, kq 0..3).
//   Warp (nt,kq): m16 x n8 x k256 (k range [kq*256,+256)), 3-pass fp16 mma.
//   Group kq (4 warps) stages its own 16KB chunk, waits, then NAMED barrier
//   (bar.sync kq+1, 128) — no full-CTA syncs in the load/compute path.
//   4-way k combine via scratch; per-bt-group grid barrier.
// SMEM: WHI[32][1032] | WLO | HS[4 kq][2 pl][16][264] | scratch 3*128*5 fl
// ---------------------------------------------------------------------------
#define RW   1032
#define RHP2 264            // staging row pitch (halves); 528B = 33 units, cf
#define CHH  8448           // halves per kq chunk (2*16*264)
#define RSM_BYTES 207360
__global__ __launch_bounds__(512) void rnn_rec_f16_kernel(
    const float* __restrict__ W,
    float* __restrict__ out)
{
    extern __shared__ __half sh[];
    __half* WHI = sh;                        // 33024 halves
    __half* WLO = sh + 33024;
    __half* HS  = sh + 66048;                // 4 * 8448 halves
    float* scratch = (float*)((char*)sh + 199680);   // [3][128][5] floats

    const int tid   = threadIdx.x;
    const int lane  = tid & 31;
    const int w     = tid >> 5;
    const int g     = lane >> 2;
    const int tig   = lane & 3;
    const int bt    = blockIdx.x & 3;
    const int jt    = blockIdx.x >> 2;
    const int jbase = jt * 32;
    const int mrow0 = bt * 16;
    const int nt    = w >> 2;       // 0..3 (n8 tile)
    const int kq    = w & 3;        // 0..3 (k quarter)
    const int tg    = nt * 32 + lane;   // index within kq group (0..127)

    // ---- pre-split W rows jbase..jbase+31 (once) ----
    for (int i = tid; i < 32 * 1024; i += 512) {
        int r = i >> 10, col = i & 1023;
        float v = W[(size_t)(jbase + r) * HID + col];
        float h = mask13(v);
        WHI[r * RW + col] = __float2half_rn(h);
        WLO[r * RW + col] = __float2half_rn(v - h);
    }
    __syncthreads();

    // staging map within group: plane, row, 4-unit column phase
    const int s_pl  = tg >> 6;
    const int s_row = (tg >> 2) & 15;
    const int s_cc  = tg & 3;

    // ldmatrix lane addresses (bytes)
    const uint32_t hs_u   = (uint32_t)__cvta_generic_to_shared(HS);
    const uint32_t a_lane = (uint32_t)(((lane & 7) + ((lane >> 3) & 1) * 8) * (RHP2 * 2)
                                       + (lane >> 4) * 16);
    const uint32_t whi_u  = (uint32_t)__cvta_generic_to_shared(WHI);
    const uint32_t wlo_u  = (uint32_t)__cvta_generic_to_shared(WLO);
    const uint32_t b_lane = (uint32_t)((nt * 8 + (lane & 7)) * (RW * 2)
                                       + ((lane >> 3) & 1) * 16);

    unsigned* my_cnt = &g_cnt[bt * 64];
    volatile unsigned* my_ph = &g_ph[bt * 64 + 32];

    for (int t = 0; t < SEQ; t++) {
        float* o0 = out + ((size_t)t * BATCH + mrow0 + g) * HID + jbase + nt * 8 + 2 * tig;
        float* o1 = o0 + (size_t)8 * HID;
        float2 xw0, xw1;
        if (kq == 0) {
            xw0 = *(const float2*)o0;
            xw1 = *(const float2*)o1;
        }

        float ahh[4] = {0.f, 0.f, 0.f, 0.f};
        float alh[4] = {0.f, 0.f, 0.f, 0.f};
        float ahl[4] = {0.f, 0.f, 0.f, 0.f};

        if (t > 0) {
            const int rp = (t - 1) & 1;
            const __half* gsrc = (s_pl == 0)
                ? g_Hhi[rp] + (size_t)(mrow0 + s_row) * HID
                : g_Hlo[rp] + (size_t)(mrow0 + s_row) * HID;

            // ---- group-private staging of chunk kq (8 cp.async16/thread) ----
            __half* dst = HS + kq * CHH + s_pl * (16 * RHP2) + s_row * RHP2;
            const __half* src = gsrc + kq * 256;
#pragma unroll
            for (int u = 0; u < 8; u++) {
                int unit = s_cc + u * 4;          // 16B unit 0..31
                cp_async16(dst + unit * 8, src + unit * 8);
            }
            cp_commit();
            cp_wait0();
            // group barrier: all 4 warps of group kq staged + landed
            asm volatile("bar.sync %0, %1;" :: "r"(kq + 1), "r"(128) : "memory");

            // ---- compute: 16 x k16 over chunk kq, no further syncs ----
            uint32_t a_hi_ad = hs_u + (uint32_t)(kq * CHH * 2) + a_lane;
            uint32_t a_lo_ad = a_hi_ad + (uint32_t)(16 * RHP2 * 2);
            uint32_t b_hi_ad = whi_u + (uint32_t)(kq * 256 * 2) + b_lane;
            uint32_t b_lo_ad = wlo_u + (uint32_t)(kq * 256 * 2) + b_lane;

#pragma unroll 8
            for (int kk = 0; kk < 16; kk++) {
                uint32_t ah[4], al[4], bh[2], bl[2];
                ldsm_x4(ah, a_hi_ad);
                ldsm_x4(al, a_lo_ad);
                ldsm_x2(bh, b_hi_ad);
                ldsm_x2(bl, b_lo_ad);
                a_hi_ad += 32; a_lo_ad += 32;
                b_hi_ad += 32; b_lo_ad += 32;

                mma_f16(ahh, ah[0], ah[1], ah[2], ah[3], bh[0], bh[1]);
                mma_f16(alh, al[0], al[1], al[2], al[3], bh[0], bh[1]);
                mma_f16(ahl, ah[0], ah[1], ah[2], ah[3], bl[0], bl[1]);
            }
        }

        // ---- combine k-quarters via scratch, tanh, store fp32 + split fp16 --
        if (kq != 0) {
            float* s = scratch + ((kq - 1) * 128 + nt * 32 + lane) * 5;
            s[0] = ahh[0] + alh[0] + ahl[0];
            s[1] = ahh[1] + alh[1] + ahl[1];
            s[2] = ahh[2] + alh[2] + ahl[2];
            s[3] = ahh[3] + alh[3] + ahl[3];
        }
        __syncthreads();
        if (kq == 0) {
            const float* s1 = scratch + (0 * 128 + nt * 32 + lane) * 5;
            const float* s2 = scratch + (1 * 128 + nt * 32 + lane) * 5;
            const float* s3 = scratch + (2 * 128 + nt * 32 + lane) * 5;
            float v00 = tanhf(xw0.x + ahh[0] + alh[0] + ahl[0] + s1[0] + s2[0] + s3[0]);
            float v01 = tanhf(xw0.y + ahh[1] + alh[1] + ahl[1] + s1[1] + s2[1] + s3[1]);
            float v10 = tanhf(xw1.x + ahh[2] + alh[2] + ahl[2] + s1[2] + s2[2] + s3[2]);
            float v11 = tanhf(xw1.y + ahh[3] + alh[3] + ahl[3] + s1[3] + s2[3] + s3[3]);

            *(float2*)o0 = make_float2(v00, v01);
            *(float2*)o1 = make_float2(v10, v11);

            const int wp = t & 1;
            __half* Hh = g_Hhi[wp];
            __half* Hl = g_Hlo[wp];
            const size_t i0 = (size_t)(mrow0 + g) * HID + jbase + nt * 8 + 2 * tig;
            const size_t i1 = i0 + (size_t)8 * HID;
            float h00 = mask13(v00), h01 = mask13(v01);
            float h10 = mask13(v10), h11 = mask13(v11);
            *(__half2*)(Hh + i0) = __floats2half2_rn(h00, h01);
            *(__half2*)(Hl + i0) = __floats2half2_rn(v00 - h00, v01 - h01);
            *(__half2*)(Hh + i1) = __floats2half2_rn(h10, h11);
            *(__half2*)(Hl + i1) = __floats2half2_rn(v10 - h10, v11 - h11);
        }

        // ---- per-bt-group grid barrier (32 arrivals, monotonic) ----
        if (t < SEQ - 1) {
            __syncthreads();
            if (tid == 0) {
                __threadfence();
                if (atomicAdd(my_cnt, 1u) == (unsigned)(32 * (t + 1) - 1)) {
                    *my_ph = (unsigned)(t + 1);
                } else {
                    while (*my_ph < (unsigned)(t + 1)) { }
                    __threadfence();
                }
            }
            __syncthreads();
        }
    }
}

// ---------------------------------------------------------------------------
__global__ void copy_hn_kernel(const float* __restrict__ src,
                               float* __restrict__ dst)
{
    int i = blockIdx.x * blockDim.x + threadIdx.x;
    float4 v = ((const float4*)src)[i];
    ((float4*)dst)[i] = v;
}

// ---------------------------------------------------------------------------
extern "C" void kernel_launch(void* const* d_in, const int* in_sizes, int n_in,
                              void* d_out, int out_size)
{
    (void)in_sizes; (void)n_in; (void)out_size;
    const float* x    = (const float*)d_in[0];
    const float* W_ih = (const float*)d_in[1];
    const float* W_hh = (const float*)d_in[2];
    const float* b_ih = (const float*)d_in[3];
    const float* b_hh = (const float*)d_in[4];
    float* out = (float*)d_out;

    cudaFuncSetAttribute(gemm_xw_f16_kernel,
                         cudaFuncAttributeMaxDynamicSharedMemorySize, 81920);
    cudaFuncSetAttribute(rnn_rec_f16_kernel,
                         cudaFuncAttributeMaxDynamicSharedMemorySize, RSM_BYTES);

    init_sync_kernel<<<1, 256>>>();

    split_x_kernel<<<(SEQ * BATCH * INDIM / 4) / 256, 256>>>(x);
    split_w_kernel<<<(HID * INDIM / 4) / 256, 256>>>(W_ih);

    dim3 g1(HID / 128, (SEQ * BATCH) / 128);
    gemm_xw_f16_kernel<<<g1, 256, 81920>>>(b_ih, b_hh, out);

    rnn_rec_f16_kernel<<<128, 512, RSM_BYTES>>>(W_hh, out);

    copy_hn_kernel<<<(BATCH * HID / 4) / 256, 256>>>(
        out + (size_t)(SEQ - 1) * BATCH * HID,
        out + (size_t)SEQ * BATCH * HID);
}

// round 17
// speedup vs baseline: 1.1700x; 1.1700x over previous
#include <cuda_runtime.h>
#include <cuda_fp16.h>
#include <math.h>
#include <cstdint>

#define SEQ   512
#define BATCH 64
#define INDIM 1024
#define HID   1024

// ---------------- device scratch (static: allowed) ----------------
__device__ __half g_Xhi[SEQ * BATCH * INDIM];
__device__ __half g_Xlo[SEQ * BATCH * INDIM];
__device__ __half g_Whi[HID * INDIM];
__device__ __half g_Wlo[HID * INDIM];
__device__ __half g_Hhi[2][BATCH * HID];
__device__ __half g_Hlo[2][BATCH * HID];

// per-(bt, chunk) producer flags; each on its own 128B line: index (bt*4+c)*32
__device__ unsigned g_ck[512];

__global__ void init_sync_kernel() {
    g_ck[threadIdx.x] = 0u;
}

// ---------------------------------------------------------------------------
__device__ __forceinline__ void cp_async16(void* smem_dst, const void* gsrc) {
    unsigned d = (unsigned)__cvta_generic_to_shared(smem_dst);
    asm volatile("cp.async.cg.shared.global [%0], [%1], 16;\n" :: "r"(d), "l"(gsrc));
}
__device__ __forceinline__ void cp_commit() { asm volatile("cp.async.commit_group;\n"); }
__device__ __forceinline__ void cp_wait0()  { asm volatile("cp.async.wait_group 0;\n"); }
__device__ __forceinline__ void cp_wait1()  { asm volatile("cp.async.wait_group 1;\n"); }

__device__ __forceinline__ float mask13(float v) {
    return __uint_as_float(__float_as_uint(v) & 0xFFFFE000u);
}

__device__ __forceinline__ void mma_f16(float* d,
                                        uint32_t a0, uint32_t a1, uint32_t a2, uint32_t a3,
                                        uint32_t b0, uint32_t b1) {
    asm volatile(
        "mma.sync.aligned.m16n8k16.row.col.f32.f16.f16.f32 "
        "{%0,%1,%2,%3}, {%4,%5,%6,%7}, {%8,%9}, {%0,%1,%2,%3};"
        : "+f"(d[0]), "+f"(d[1]), "+f"(d[2]), "+f"(d[3])
        : "r"(a0), "r"(a1), "r"(a2), "r"(a3), "r"(b0), "r"(b1));
}

__device__ __forceinline__ void ldsm_x4(uint32_t* r, uint32_t a) {
    asm volatile("ldmatrix.sync.aligned.m8n8.x4.shared.b16 {%0,%1,%2,%3}, [%4];"
        : "=r"(r[0]), "=r"(r[1]), "=r"(r[2]), "=r"(r[3]) : "r"(a));
}
__device__ __forceinline__ void ldsm_x2(uint32_t* r, uint32_t a) {
    asm volatile("ldmatrix.sync.aligned.m8n8.x2.shared.b16 {%0,%1}, [%2];"
        : "=r"(r[0]), "=r"(r[1]) : "r"(a));
}

__device__ __forceinline__ void wait_flag(volatile unsigned* f, unsigned tgt) {
    while (*f < tgt) { }
}

// ---------------------------------------------------------------------------
// Split kernels: fp32 -> fp16 hi/lo planes
// ---------------------------------------------------------------------------
__global__ void split_x_kernel(const float* __restrict__ src) {
    int i = blockIdx.x * 256 + threadIdx.x;
    float4 v = ((const float4*)src)[i];
    float h0 = mask13(v.x), h1 = mask13(v.y), h2 = mask13(v.z), h3 = mask13(v.w);
    ((__half2*)g_Xhi)[2 * i]     = __floats2half2_rn(h0, h1);
    ((__half2*)g_Xhi)[2 * i + 1] = __floats2half2_rn(h2, h3);
    ((__half2*)g_Xlo)[2 * i]     = __floats2half2_rn(v.x - h0, v.y - h1);
    ((__half2*)g_Xlo)[2 * i + 1] = __floats2half2_rn(v.z - h2, v.w - h3);
}
__global__ void split_w_kernel(const float* __restrict__ src) {
    int i = blockIdx.x * 256 + threadIdx.x;
    float4 v = ((const float4*)src)[i];
    float h0 = mask13(v.x), h1 = mask13(v.y), h2 = mask13(v.z), h3 = mask13(v.w);
    ((__half2*)g_Whi)[2 * i]     = __floats2half2_rn(h0, h1);
    ((__half2*)g_Whi)[2 * i + 1] = __floats2half2_rn(h2, h3);
    ((__half2*)g_Wlo)[2 * i]     = __floats2half2_rn(v.x - h0, v.y - h1);
    ((__half2*)g_Wlo)[2 * i + 1] = __floats2half2_rn(v.z - h2, v.w - h3);
}

// ---------------------------------------------------------------------------
// Phase 1: C = x @ W_ih^T + bias. fp16 3-pass MMA, scalar LDS loads (best).
// ---------------------------------------------------------------------------
#define P1P 40
__global__ __launch_bounds__(256) void gemm_xw_f16_kernel(
    const float* __restrict__ bih,
    const float* __restrict__ bhh,
    float* __restrict__ C)
{
    extern __shared__ __half sh[];
    __half* Ahi = sh;
    __half* Alo = sh + 10240;
    __half* Bhi = sh + 20480;
    __half* Blo = sh + 30720;

    const int tid    = threadIdx.x;
    const int lane   = tid & 31;
    const int wid    = tid >> 5;
    const int g      = lane >> 2;
    const int tig    = lane & 3;
    const int warp_m = wid & 1;
    const int warp_n = wid >> 1;
    const int bm     = blockIdx.y * 128;
    const int bn     = blockIdx.x * 128;

    float acc[4][4][4];
#pragma unroll
    for (int i = 0; i < 4; i++)
#pragma unroll
        for (int j = 0; j < 4; j++)
#pragma unroll
            for (int c = 0; c < 4; c++) acc[i][j][c] = 0.0f;

    const int srow = tid >> 2;
    const int sch  = tid & 3;

    auto stage = [&](int c) {
        const int bo = (c & 1) * 5120;
        const int kc = c * 32;
#pragma unroll
        for (int u = 0; u < 2; u++) {
            int row = srow + u * 64;
            size_t aoff = (size_t)(bm + row) * INDIM + kc + sch * 8;
            size_t boff = (size_t)(bn + row) * INDIM + kc + sch * 8;
            cp_async16(Ahi + bo + row * P1P + sch * 8, g_Xhi + aoff);
            cp_async16(Alo + bo + row * P1P + sch * 8, g_Xlo + aoff);
            cp_async16(Bhi + bo + row * P1P + sch * 8, g_Whi + boff);
            cp_async16(Blo + bo + row * P1P + sch * 8, g_Wlo + boff);
        }
        cp_commit();
    };

    stage(0);

    for (int c = 0; c < INDIM / 32; c++) {
        if (c + 1 < INDIM / 32) { stage(c + 1); cp_wait1(); }
        else                    { cp_wait0(); }
        __syncthreads();

        const int bo = (c & 1) * 5120;
        const __half* Aph = Ahi + bo + warp_m * 64 * P1P;
        const __half* Apl = Alo + bo + warp_m * 64 * P1P;
        const __half* Bph = Bhi + bo + warp_n * 32 * P1P;
        const __half* Bpl = Blo + bo + warp_n * 32 * P1P;

#pragma unroll
        for (int kg = 0; kg < 2; kg++) {
            const int ko = kg * 16 + 2 * tig;

            uint32_t ah[4][4], al[4][4];
#pragma unroll
            for (int mt = 0; mt < 4; mt++) {
                int base = (mt * 16 + g) * P1P + ko;
                ah[mt][0] = *(const uint32_t*)&Aph[base];
                ah[mt][1] = *(const uint32_t*)&Aph[base + 8 * P1P];
                ah[mt][2] = *(const uint32_t*)&Aph[base + 8];
                ah[mt][3] = *(const uint32_t*)&Aph[base + 8 * P1P + 8];
                al[mt][0] = *(const uint32_t*)&Apl[base];
                al[mt][1] = *(const uint32_t*)&Apl[base + 8 * P1P];
                al[mt][2] = *(const uint32_t*)&Apl[base + 8];
                al[mt][3] = *(const uint32_t*)&Apl[base + 8 * P1P + 8];
            }
            uint32_t bh[4][2], bl[4][2];
#pragma unroll
            for (int nt = 0; nt < 4; nt++) {
                int sb = (nt * 8 + g) * P1P + ko;
                bh[nt][0] = *(const uint32_t*)&Bph[sb];
                bh[nt][1] = *(const uint32_t*)&Bph[sb + 8];
                bl[nt][0] = *(const uint32_t*)&Bpl[sb];
                bl[nt][1] = *(const uint32_t*)&Bpl[sb + 8];
            }
#pragma unroll
            for (int mt = 0; mt < 4; mt++) {
#pragma unroll
                for (int nt = 0; nt < 4; nt++) {
                    mma_f16(acc[mt][nt], ah[mt][0], ah[mt][1], ah[mt][2], ah[mt][3],
                            bh[nt][0], bh[nt][1]);
                    mma_f16(acc[mt][nt], al[mt][0], al[mt][1], al[mt][2], al[mt][3],
                            bh[nt][0], bh[nt][1]);
                    mma_f16(acc[mt][nt], ah[mt][0], ah[mt][1], ah[mt][2], ah[mt][3],
                            bl[nt][0], bl[nt][1]);
                }
            }
        }
        __syncthreads();
    }

#pragma unroll
    for (int nt = 0; nt < 4; nt++) {
        const int n0 = bn + warp_n * 32 + nt * 8 + 2 * tig;
        const float bv0 = bih[n0] + bhh[n0];
        const float bv1 = bih[n0 + 1] + bhh[n0 + 1];
#pragma unroll
        for (int mt = 0; mt < 4; mt++) {
            const int m0 = bm + warp_m * 64 + mt * 16 + g;
            float2 lo2, hi2;
            lo2.x = acc[mt][nt][0] + bv0;
            lo2.y = acc[mt][nt][1] + bv1;
            hi2.x = acc[mt][nt][2] + bv0;
            hi2.y = acc[mt][nt][3] + bv1;
            *(float2*)(C + (size_t)m0 * HID + n0)       = lo2;
            *(float2*)(C + (size_t)(m0 + 8) * HID + n0) = hi2;
        }
    }
}

// ---------------------------------------------------------------------------
// Phase 2: persistent recurrence with DATAFLOW sync (no grid barrier).
//   128 CTAs = (bt = bid&3) x (jt = bid>>2). CTA: m16 rows, n32 j cols.
//   8 warps = (nt = w>>1) x (kh = w&1). Chunk c = k in [256c, 256c+256);
//   producers of chunk c = CTAs jt in [8c, 8c+8); flag g_ck[(bt*4+c)*32]
//   incremented once per step by each producer. Consumers poll the flag
//   before staging chunk c -> skew absorbed per chunk, no max-reduce.
//   kh group (4 warps, 128 thr) stages + computes chunks {2kh, 2kh+1} with
//   a named barrier; 2 full-CTA syncs per step (combine + reuse/arrive).
// SMEM: WHI[32][1032] | WLO | HS[4][2pl][16][264] | scratch [4][32][5] fl
// ---------------------------------------------------------------------------
#define RW   1032
#define RHP2 264
#define CHH  8448                 // halves per chunk buffer
#define RSM_BYTES 202240
__global__ __launch_bounds__(256) void rnn_rec_f16_kernel(
    const float* __restrict__ W,
    float* __restrict__ out)
{
    extern __shared__ __half sh[];
    __half* WHI = sh;                        // 33024 halves
    __half* WLO = sh + 33024;
    __half* HS  = sh + 66048;                // 4 * 8448 halves
    float* scratch = (float*)((char*)sh + 199680);   // [4][32][5] floats

    const int tid   = threadIdx.x;
    const int lane  = tid & 31;
    const int w     = tid >> 5;
    const int g     = lane >> 2;
    const int tig   = lane & 3;
    const int bt    = blockIdx.x & 3;
    const int jt    = blockIdx.x >> 2;
    const int jbase = jt * 32;
    const int mrow0 = bt * 16;
    const int nt    = w >> 1;
    const int kh    = w & 1;

    // ---- pre-split W rows jbase..jbase+31 (once) ----
    for (int i = tid; i < 32 * 1024; i += 256) {
        int r = i >> 10, col = i & 1023;
        float v = W[(size_t)(jbase + r) * HID + col];
        float h = mask13(v);
        WHI[r * RW + col] = __float2half_rn(h);
        WLO[r * RW + col] = __float2half_rn(v - h);
    }
    __syncthreads();

    // staging map within kh group (tg = 0..127)
    const int tg    = nt * 32 + lane;
    const int s_pl  = tg >> 6;
    const int s_row = (tg >> 2) & 15;
    const int s_cc  = tg & 3;

    // ldmatrix lane addresses (bytes)
    const uint32_t hs_u   = (uint32_t)__cvta_generic_to_shared(HS);
    const uint32_t a_lane = (uint32_t)(((lane & 7) + ((lane >> 3) & 1) * 8) * (RHP2 * 2)
                                       + (lane >> 4) * 16);
    const uint32_t whi_u  = (uint32_t)__cvta_generic_to_shared(WHI);
    const uint32_t wlo_u  = (uint32_t)__cvta_generic_to_shared(WLO);
    const uint32_t b_lane = (uint32_t)((nt * 8 + (lane & 7)) * (RW * 2)
                                       + ((lane >> 3) & 1) * 16);

    // flags
    volatile unsigned* flag_base = (volatile unsigned*)&g_ck[bt * 4 * 32];
    unsigned* my_arrive = &g_ck[(bt * 4 + (jt >> 3)) * 32];
    const int c0 = kh * 2, c1 = kh * 2 + 1;

    for (int t = 0; t < SEQ; t++) {
        float* o0 = out + ((size_t)t * BATCH + mrow0 + g) * HID + jbase + nt * 8 + 2 * tig;
        float* o1 = o0 + (size_t)8 * HID;
        float2 xw0, xw1;
        if (kh == 0) {
            xw0 = *(const float2*)o0;
            xw1 = *(const float2*)o1;
        }

        float ahh[4] = {0.f, 0.f, 0.f, 0.f};
        float alh[4] = {0.f, 0.f, 0.f, 0.f};
        float ahl[4] = {0.f, 0.f, 0.f, 0.f};

        if (t > 0) {
            const unsigned target = 8u * (unsigned)t;
            const int rp = (t - 1) & 1;
            const __half* gsrc = (s_pl == 0)
                ? g_Hhi[rp] + (size_t)(mrow0 + s_row) * HID
                : g_Hlo[rp] + (size_t)(mrow0 + s_row) * HID;

            auto stage = [&](int c) {
                __half* dst = HS + c * CHH + s_pl * (16 * RHP2) + s_row * RHP2;
                const __half* src = gsrc + c * 256;
#pragma unroll
                for (int u = 0; u < 8; u++) {
                    int unit = s_cc + u * 4;          // 16B unit 0..31
                    cp_async16(dst + unit * 8, src + unit * 8);
                }
                cp_commit();
            };

            // poll flag, then stage (chunks of this kh group)
            wait_flag(flag_base + c0 * 32, target);
            stage(c0);
            wait_flag(flag_base + c1 * 32, target);
            stage(c1);

#pragma unroll
            for (int cc = 0; cc < 2; cc++) {
                const int c = c0 + cc;
                if (cc == 0) cp_wait1(); else cp_wait0();
                asm volatile("bar.sync %0, %1;" :: "r"(kh + 1), "r"(128) : "memory");

                uint32_t a_hi_ad = hs_u + (uint32_t)(c * CHH * 2) + a_lane;
                uint32_t a_lo_ad = a_hi_ad + (uint32_t)(16 * RHP2 * 2);
                uint32_t b_hi_ad = whi_u + (uint32_t)(c * 256 * 2) + b_lane;
                uint32_t b_lo_ad = wlo_u + (uint32_t)(c * 256 * 2) + b_lane;

#pragma unroll 8
                for (int kk = 0; kk < 16; kk++) {
                    uint32_t ah[4], al[4], bh[2], bl[2];
                    ldsm_x4(ah, a_hi_ad);
                    ldsm_x4(al, a_lo_ad);
                    ldsm_x2(bh, b_hi_ad);
                    ldsm_x2(bl, b_lo_ad);
                    a_hi_ad += 32; a_lo_ad += 32;
                    b_hi_ad += 32; b_lo_ad += 32;

                    mma_f16(ahh, ah[0], ah[1], ah[2], ah[3], bh[0], bh[1]);
                    mma_f16(alh, al[0], al[1], al[2], al[3], bh[0], bh[1]);
                    mma_f16(ahl, ah[0], ah[1], ah[2], ah[3], bl[0], bl[1]);
                }
            }
        }

        // ---- combine k-halves via scratch, tanh, store fp32 + split fp16 ----
        if (kh == 1) {
            float* s = scratch + (nt * 32 + lane) * 5;
            s[0] = ahh[0] + alh[0] + ahl[0];
            s[1] = ahh[1] + alh[1] + ahl[1];
            s[2] = ahh[2] + alh[2] + ahl[2];
            s[3] = ahh[3] + alh[3] + ahl[3];
        }
        __syncthreads();
        if (kh == 0) {
            const float* s = scratch + (nt * 32 + lane) * 5;
            float v00 = tanhf(xw0.x + ahh[0] + alh[0] + ahl[0] + s[0]);
            float v01 = tanhf(xw0.y + ahh[1] + alh[1] + ahl[1] + s[1]);
            float v10 = tanhf(xw1.x + ahh[2] + alh[2] + ahl[2] + s[2]);
            float v11 = tanhf(xw1.y + ahh[3] + alh[3] + ahl[3] + s[3]);

            *(float2*)o0 = make_float2(v00, v01);
            *(float2*)o1 = make_float2(v10, v11);

            const int wp = t & 1;
            __half* Hh = g_Hhi[wp];
            __half* Hl = g_Hlo[wp];
            const size_t i0 = (size_t)(mrow0 + g) * HID + jbase + nt * 8 + 2 * tig;
            const size_t i1 = i0 + (size_t)8 * HID;
            float h00 = mask13(v00), h01 = mask13(v01);
            float h10 = mask13(v10), h11 = mask13(v11);
            *(__half2*)(Hh + i0) = __floats2half2_rn(h00, h01);
            *(__half2*)(Hl + i0) = __floats2half2_rn(v00 - h00, v01 - h01);
            *(__half2*)(Hh + i1) = __floats2half2_rn(h10, h11);
            *(__half2*)(Hl + i1) = __floats2half2_rn(v10 - h10, v11 - h11);
        }

        // ---- producer arrival (replaces the grid barrier) ----
        __syncthreads();    // stores issued by kh0; compute finished by all
        if (t < SEQ - 1) {
            if (tid == 0) {
                __threadfence();
                atomicAdd(my_arrive, 1u);
            }
        }
    }
}

// ---------------------------------------------------------------------------
__global__ void copy_hn_kernel(const float* __restrict__ src,
                               float* __restrict__ dst)
{
    int i = blockIdx.x * blockDim.x + threadIdx.x;
    float4 v = ((const float4*)src)[i];
    ((float4*)dst)[i] = v;
}

// ---------------------------------------------------------------------------
extern "C" void kernel_launch(void* const* d_in, const int* in_sizes, int n_in,
                              void* d_out, int out_size)
{
    (void)in_sizes; (void)n_in; (void)out_size;
    const float* x    = (const float*)d_in[0];
    const float* W_ih = (const float*)d_in[1];
    const float* W_hh = (const float*)d_in[2];
    const float* b_ih = (const float*)d_in[3];
    const float* b_hh = (const float*)d_in[4];
    float* out = (float*)d_out;

    cudaFuncSetAttribute(gemm_xw_f16_kernel,
                         cudaFuncAttributeMaxDynamicSharedMemorySize, 81920);
    cudaFuncSetAttribute(rnn_rec_f16_kernel,
                         cudaFuncAttributeMaxDynamicSharedMemorySize, RSM_BYTES);

    init_sync_kernel<<<1, 512>>>();

    split_x_kernel<<<(SEQ * BATCH * INDIM / 4) / 256, 256>>>(x);
    split_w_kernel<<<(HID * INDIM / 4) / 256, 256>>>(W_ih);

    dim3 g1(HID / 128, (SEQ * BATCH) / 128);
    gemm_xw_f16_kernel<<<g1, 256, 81920>>>(b_ih, b_hh, out);

    rnn_rec_f16_kernel<<<128, 256, RSM_BYTES>>>(W_hh, out);

    copy_hn_kernel<<<(BATCH * HID / 4) / 256, 256>>>(
        out + (size_t)(SEQ - 1) * BATCH * HID,
        out + (size_t)SEQ * BATCH * HID);
}